// round 7
// baseline (speedup 1.0000x reference)
#include <cuda_runtime.h>
#include <cstdint>

// Problem constants (fixed by the reference: n=4096, d=2048, num_ids=256)
#define N_ROWS     4096
#define DCOLS      2048
#define ROW_BYTES  (DCOLS * 4)            // 8192 bytes per row
#define CHUNK_ROWS 4
#define CHUNK_BYTES (CHUNK_ROWS * ROW_BYTES)  // 32768
#define P2_CHUNKS  2048                   // 8192 pair2 rows / 4
#define P1_CHUNKS  1024                   // 4096 input rows / 4

// ---------------------------------------------------------------------------
// PTX helpers
// ---------------------------------------------------------------------------
__device__ __forceinline__ uint32_t smem_u32(const void* p) {
    uint32_t a;
    asm("{ .reg .u64 tmp; cvta.to.shared.u64 tmp, %1; cvt.u32.u64 %0, tmp; }"
        : "=r"(a) : "l"(p));
    return a;
}

__device__ __forceinline__ void mbar_init(uint32_t mbar, uint32_t count) {
    asm volatile("mbarrier.init.shared.b64 [%0], %1;" :: "r"(mbar), "r"(count) : "memory");
}
__device__ __forceinline__ void mbar_expect_tx(uint32_t mbar, uint32_t bytes) {
    asm volatile("mbarrier.arrive.expect_tx.shared.b64 _, [%0], %1;"
                 :: "r"(mbar), "r"(bytes) : "memory");
}
__device__ __forceinline__ void mbar_wait(uint32_t mbar, uint32_t parity) {
    asm volatile(
        "{\n\t"
        ".reg .pred P;\n\t"
        "WAIT_%=:\n\t"
        "mbarrier.try_wait.parity.shared.b64 P, [%0], %1;\n\t"
        "@P bra.uni DONE_%=;\n\t"
        "bra.uni WAIT_%=;\n\t"
        "DONE_%=:\n\t"
        "}" :: "r"(mbar), "r"(parity) : "memory");
}

// 1D bulk TMA: global -> shared::cta, completion via mbarrier tx bytes.
__device__ __forceinline__ void bulk_g2s(uint32_t smem_dst, const void* gmem_src,
                                         uint32_t bytes, uint32_t mbar) {
    asm volatile(
        "cp.async.bulk.shared::cta.global.mbarrier::complete_tx::bytes "
        "[%0], [%1], %2, [%3];"
        :: "r"(smem_dst), "l"(gmem_src), "r"(bytes), "r"(mbar) : "memory");
}
// 1D bulk TMA: shared::cta -> global, bulk_group completion.
__device__ __forceinline__ void bulk_s2g(void* gmem_dst, uint32_t smem_src,
                                         uint32_t bytes) {
    asm volatile(
        "cp.async.bulk.global.shared::cta.bulk_group [%0], [%1], %2;"
        :: "l"(gmem_dst), "r"(smem_src), "r"(bytes) : "memory");
}
__device__ __forceinline__ void bulk_commit() {
    asm volatile("cp.async.bulk.commit_group;" ::: "memory");
}
__device__ __forceinline__ void bulk_wait_all() {
    asm volatile("cp.async.bulk.wait_group.read 0;" ::: "memory");
}

// ---------------------------------------------------------------------------
// Bit-exact JAX threefry-2x32 (20 rounds)
// ---------------------------------------------------------------------------
__device__ __forceinline__ void threefry2x32(uint32_t k0, uint32_t k1,
                                             uint32_t c0, uint32_t c1,
                                             uint32_t& o0, uint32_t& o1) {
    const uint32_t ks2 = k0 ^ k1 ^ 0x1BD11BDAu;
    uint32_t x0 = c0 + k0;
    uint32_t x1 = c1 + k1;
#define TF_ROUND(r) { x0 += x1; x1 = (x1 << (r)) | (x1 >> (32 - (r))); x1 ^= x0; }
    TF_ROUND(13) TF_ROUND(15) TF_ROUND(26) TF_ROUND(6)
    x0 += k1;  x1 += ks2 + 1u;
    TF_ROUND(17) TF_ROUND(29) TF_ROUND(16) TF_ROUND(24)
    x0 += ks2; x1 += k0 + 2u;
    TF_ROUND(13) TF_ROUND(15) TF_ROUND(26) TF_ROUND(6)
    x0 += k0;  x1 += k1 + 3u;
    TF_ROUND(17) TF_ROUND(29) TF_ROUND(16) TF_ROUND(24)
    x0 += k1;  x1 += ks2 + 4u;
    TF_ROUND(13) TF_ROUND(15) TF_ROUND(26) TF_ROUND(6)
    x0 += ks2; x1 += k0 + 5u;
#undef TF_ROUND
    o0 = x0; o1 = x1;
}

// jax.random.uniform f32: bitcast(0x3F800000 | (bits >> 9)) - 1
__device__ __forceinline__ float bits_to_uniform(uint32_t b) {
    return __uint_as_float(0x3F800000u | (b >> 9)) - 1.0f;
}

// Partitionable threefry random bits for element i: counter=(0,i), out = o0^o1.
__device__ __forceinline__ uint32_t jax_bits32(uint32_t key_lo, uint32_t i) {
    uint32_t o0, o1;
    threefry2x32(0u, key_lo, 0u, i, o0, o1);
    return o0 ^ o1;
}

// ---------------------------------------------------------------------------
// fused TMA kernel, single launch.
//   Blocks [0, 2048):    pair2 chunk q: rows [q*4, q*4+4) of 8192.
//       256 threads compute the 4 gather indices (targets scan + threefry),
//       then thread 0 issues 4x 8KB bulk loads (gathered rows) -> one 32KB
//       bulk store to the contiguous pair2 destination.
//   Blocks [2048, 3072): pair1 chunk p: input rows [p*4, p*4+4).
//       thread 0: one 32KB bulk load, two 32KB bulk stores (rows r, r+4096).
//       First 16 pair1 blocks also write y via normal stores.
// ---------------------------------------------------------------------------
__global__ void __launch_bounds__(256)
fused_tma_kernel(const char* __restrict__ in,
                 const int* __restrict__ targets,
                 char* __restrict__ out,
                 float* __restrict__ y_out) {
    __shared__ alignas(128) char buf[CHUNK_BYTES];
    __shared__ alignas(8) unsigned long long mbar_storage;
    __shared__ int s_tgt[4];
    __shared__ int s_cnt[4];
    __shared__ int s_src[4];

    const int t = threadIdx.x;
    const int b = blockIdx.x;
    const uint32_t sbuf  = smem_u32(buf);
    const uint32_t smbar = smem_u32(&mbar_storage);

    if (b < P2_CHUNKS) {
        // ---------------- pair2 ----------------
        const int row0 = b * 4;                    // pair2 row in [0, 8192)
        if (t < 4) {
            s_tgt[t] = targets[(row0 + t) & (N_ROWS - 1)];
            s_cnt[t] = 0;
        }
        if (t == 0) mbar_init(smbar, 1);
        __syncthreads();

        // Same-identity counts for the 4 rows by direct comparison (16 KB scan)
        const int t0 = s_tgt[0], t1 = s_tgt[1], t2 = s_tgt[2], t3 = s_tgt[3];
        int c0 = 0, c1 = 0, c2 = 0, c3 = 0;
        #pragma unroll
        for (int k = 0; k < N_ROWS / 256; ++k) {   // 16 coalesced L2-hot loads
            const int v = __ldg(&targets[k * 256 + t]);
            c0 += (v == t0); c1 += (v == t1); c2 += (v == t2); c3 += (v == t3);
        }
        #pragma unroll
        for (int off = 16; off; off >>= 1) {
            c0 += __shfl_down_sync(0xFFFFFFFFu, c0, off);
            c1 += __shfl_down_sync(0xFFFFFFFFu, c1, off);
            c2 += __shfl_down_sync(0xFFFFFFFFu, c2, off);
            c3 += __shfl_down_sync(0xFFFFFFFFu, c3, off);
        }
        if ((t & 31) == 0) {
            atomicAdd(&s_cnt[0], c0); atomicAdd(&s_cnt[1], c1);
            atomicAdd(&s_cnt[2], c2); atomicAdd(&s_cnt[3], c3);
        }
        __syncthreads();

        if (t < 4) {
            const int r  = row0 + t;
            const int i  = r & (N_ROWS - 1);       // element index for PRNG
            const int pc = s_cnt[t];
            int      cnt;
            uint32_t key;
            if (r < N_ROWS) { cnt = pc; key = 1u; }     // positives: key(1)
            else {
                cnt = N_ROWS - pc;
                if (cnt < 1) cnt = 1;
                key = 2u;                                // negatives: key(2)
            }
            const float u = bits_to_uniform(jax_bits32(key, (uint32_t)i));
            int idx = (int)(u * (float)cnt);             // f32 mul + trunc
            if (idx > cnt - 1) idx = cnt - 1;
            s_src[t] = idx;
        }
        __syncthreads();

        if (t == 0) {
            mbar_expect_tx(smbar, CHUNK_BYTES);
            #pragma unroll
            for (int rr = 0; rr < 4; ++rr)
                bulk_g2s(sbuf + rr * ROW_BYTES,
                         in + (size_t)s_src[rr] * ROW_BYTES,
                         ROW_BYTES, smbar);
            mbar_wait(smbar, 0);
            // pair2 destination rows are contiguous: one 32 KB store
            char* dst = out + ((size_t)2 * N_ROWS + row0) * ROW_BYTES;
            bulk_s2g(dst, sbuf, CHUNK_BYTES);
            bulk_commit();
            bulk_wait_all();        // smem must outlive the async store
        }
        __syncthreads();
    } else {
        // ---------------- pair1 ----------------
        const int p    = b - P2_CHUNKS;
        const int row0 = p * 4;                    // input row in [0, 4096)
        if (t == 0) {
            mbar_init(smbar, 1);
            mbar_expect_tx(smbar, CHUNK_BYTES);
            bulk_g2s(sbuf, in + (size_t)row0 * ROW_BYTES, CHUNK_BYTES, smbar);
            mbar_wait(smbar, 0);
            bulk_s2g(out + (size_t)row0 * ROW_BYTES,            sbuf, CHUNK_BYTES);
            bulk_s2g(out + (size_t)(row0 + N_ROWS) * ROW_BYTES, sbuf, CHUNK_BYTES);
            bulk_commit();
            bulk_wait_all();
        }
        // y = [1]*n ++ [0]*n : 512 floats per block for the first 16 chunks
        if (p < 16) {
            const int base = p * 512;
            y_out[base + t]       = (base + t       < N_ROWS) ? 1.0f : 0.0f;
            y_out[base + 256 + t] = (base + 256 + t < N_ROWS) ? 1.0f : 0.0f;
        }
        __syncthreads();
    }
}

// ---------------------------------------------------------------------------
// kernel_launch: inputs = d_in[0] (f32 4096x2048), targets = d_in[1] (i32 4096)
// out layout (flat f32): pair1 [2n*d] | pair2 [2n*d] | y [2n]
// ---------------------------------------------------------------------------
extern "C" void kernel_launch(void* const* d_in, const int* in_sizes, int n_in,
                              void* d_out, int out_size) {
    (void)in_sizes; (void)n_in; (void)out_size;
    const char* inputs  = (const char*)d_in[0];
    const int*  targets = (const int*)d_in[1];
    char*       out     = (char*)d_out;
    float*      y       = (float*)(out + (size_t)4 * N_ROWS * DCOLS * 4);

    fused_tma_kernel<<<P2_CHUNKS + P1_CHUNKS, 256>>>(inputs, targets, out, y);
}

// round 8
// speedup vs baseline: 1.0474x; 1.0474x over previous
#include <cuda_runtime.h>
#include <cstdint>

// Problem constants (fixed by the reference: n=4096, d=2048, num_ids=256)
#define N_ROWS 4096
#define DCOLS  2048
#define ROW_F4 (DCOLS / 4)   // 512 float4 per row
#define RPB    8             // rows per block
#define P2_BLOCKS (8192 / RPB)   // 1024  (pair2 first: scans overlap copies)
#define P1_BLOCKS (4096 / RPB)   // 512

// ---------------------------------------------------------------------------
// Bit-exact JAX threefry-2x32 (20 rounds)
// ---------------------------------------------------------------------------
__device__ __forceinline__ void threefry2x32(uint32_t k0, uint32_t k1,
                                             uint32_t c0, uint32_t c1,
                                             uint32_t& o0, uint32_t& o1) {
    const uint32_t ks2 = k0 ^ k1 ^ 0x1BD11BDAu;
    uint32_t x0 = c0 + k0;
    uint32_t x1 = c1 + k1;
#define TF_ROUND(r) { x0 += x1; x1 = (x1 << (r)) | (x1 >> (32 - (r))); x1 ^= x0; }
    TF_ROUND(13) TF_ROUND(15) TF_ROUND(26) TF_ROUND(6)
    x0 += k1;  x1 += ks2 + 1u;
    TF_ROUND(17) TF_ROUND(29) TF_ROUND(16) TF_ROUND(24)
    x0 += ks2; x1 += k0 + 2u;
    TF_ROUND(13) TF_ROUND(15) TF_ROUND(26) TF_ROUND(6)
    x0 += k0;  x1 += k1 + 3u;
    TF_ROUND(17) TF_ROUND(29) TF_ROUND(16) TF_ROUND(24)
    x0 += k1;  x1 += ks2 + 4u;
    TF_ROUND(13) TF_ROUND(15) TF_ROUND(26) TF_ROUND(6)
    x0 += ks2; x1 += k0 + 5u;
#undef TF_ROUND
    o0 = x0; o1 = x1;
}

// jax.random.uniform f32: bitcast(0x3F800000 | (bits >> 9)) - 1
__device__ __forceinline__ float bits_to_uniform(uint32_t b) {
    return __uint_as_float(0x3F800000u | (b >> 9)) - 1.0f;
}

// Partitionable threefry random bits for element i: counter=(0,i), out = o0^o1.
__device__ __forceinline__ uint32_t jax_bits32(uint32_t key_lo, uint32_t i) {
    uint32_t o0, o1;
    threefry2x32(0u, key_lo, 0u, i, o0, o1);
    return o0 ^ o1;
}

// Copy one row (512 float4) with 256 threads, loads batched 2-deep per row;
// caller interleaves two rows for 4-deep MLP.
__device__ __forceinline__ void copy2(const float4* __restrict__ sA,
                                      const float4* __restrict__ sB,
                                      float4* __restrict__ dA,
                                      float4* __restrict__ dB, int t) {
    const float4 a0 = __ldg(sA + t);
    const float4 a1 = __ldg(sA + t + 256);
    const float4 b0 = __ldg(sB + t);
    const float4 b1 = __ldg(sB + t + 256);
    __stcs(dA + t,       a0); __stcs(dA + t + 256, a1);
    __stcs(dB + t,       b0); __stcs(dB + t + 256, b1);
}

// ---------------------------------------------------------------------------
// fused_kernel, single launch, 1536 blocks x 256 threads.
//   Blocks [0, 1024):    pair2. Block q owns pair2 rows [q*8, q*8+8) of 8192.
//       Prologue: same-identity counts for the 8 rows via one pass over
//       targets (16 KB, L2-hot; 8 compares per loaded value), REDUX warp
//       reduction, then partitionable-threefry indices. Then gather-copy.
//   Blocks [1024, 1536): pair1. Block p owns input rows [p*8, p*8+8); each
//       float4 loaded once, stored to pair1 rows r and r+4096. First 16
//       blocks also write y.
// ---------------------------------------------------------------------------
__global__ void __launch_bounds__(256)
fused_kernel(const float4* __restrict__ in,
             const int* __restrict__ targets,
             float4* __restrict__ out,
             float* __restrict__ y_out) {
    const int t = threadIdx.x;
    const int b = blockIdx.x;

    if (b < P2_BLOCKS) {
        // ---------------- pair2 ----------------
        const int row0 = b * RPB;                  // pair2 row in [0, 8192)

        __shared__ int s_tgt[RPB];
        __shared__ int s_cnt[RPB];
        __shared__ int s_src[RPB];
        if (t < RPB) {
            s_tgt[t] = targets[(row0 + t) & (N_ROWS - 1)];
            s_cnt[t] = 0;
        }
        __syncthreads();

        // Counts: one coalesced pass over targets, 8 compares per value
        int c[RPB];
        #pragma unroll
        for (int j = 0; j < RPB; ++j) c[j] = 0;
        const int t0 = s_tgt[0], t1 = s_tgt[1], t2 = s_tgt[2], t3 = s_tgt[3];
        const int t4 = s_tgt[4], t5 = s_tgt[5], t6 = s_tgt[6], t7 = s_tgt[7];
        #pragma unroll
        for (int k = 0; k < N_ROWS / 256; ++k) {   // 16 L2-hot loads
            const int v = __ldg(&targets[k * 256 + t]);
            c[0] += (v == t0); c[1] += (v == t1); c[2] += (v == t2); c[3] += (v == t3);
            c[4] += (v == t4); c[5] += (v == t5); c[6] += (v == t6); c[7] += (v == t7);
        }
        #pragma unroll
        for (int j = 0; j < RPB; ++j)
            c[j] = __reduce_add_sync(0xFFFFFFFFu, c[j]);   // REDUX.SUM
        if ((t & 31) == 0) {
            #pragma unroll
            for (int j = 0; j < RPB; ++j) atomicAdd(&s_cnt[j], c[j]);
        }
        __syncthreads();

        if (t < RPB) {
            const int r  = row0 + t;
            const int i  = r & (N_ROWS - 1);       // element index for PRNG
            const int pc = s_cnt[t];
            int      cnt;
            uint32_t key;
            if (r < N_ROWS) { cnt = pc; key = 1u; }     // positives: key(1)
            else {
                cnt = N_ROWS - pc;
                if (cnt < 1) cnt = 1;
                key = 2u;                                // negatives: key(2)
            }
            const float u = bits_to_uniform(jax_bits32(key, (uint32_t)i));
            int idx = (int)(u * (float)cnt);             // f32 mul + trunc
            if (idx > cnt - 1) idx = cnt - 1;
            s_src[t] = idx;
        }
        __syncthreads();

        float4* base = out + (size_t)2 * N_ROWS * ROW_F4;  // start of pair2
        #pragma unroll
        for (int rp = 0; rp < RPB / 2; ++rp) {
            const int r0 = row0 + rp * 2;
            copy2(in + (size_t)s_src[rp * 2]     * ROW_F4,
                  in + (size_t)s_src[rp * 2 + 1] * ROW_F4,
                  base + (size_t)r0       * ROW_F4,
                  base + (size_t)(r0 + 1) * ROW_F4, t);
        }
    } else {
        // ---------------- pair1: dual store ----------------
        const int p    = b - P2_BLOCKS;
        const int row0 = p * RPB;                  // input row in [0, 4096)
        #pragma unroll
        for (int rr = 0; rr < RPB; rr += 2) {
            const int r0 = row0 + rr;
            const int r1 = r0 + 1;
            const float4* s0 = in + (size_t)r0 * ROW_F4;
            const float4* s1 = in + (size_t)r1 * ROW_F4;
            const float4 a0 = __ldg(s0 + t);
            const float4 a1 = __ldg(s0 + t + 256);
            const float4 b0 = __ldg(s1 + t);
            const float4 b1 = __ldg(s1 + t + 256);
            float4* dA0 = out + (size_t)r0 * ROW_F4;
            float4* dB0 = out + (size_t)(r0 + N_ROWS) * ROW_F4;
            float4* dA1 = out + (size_t)r1 * ROW_F4;
            float4* dB1 = out + (size_t)(r1 + N_ROWS) * ROW_F4;
            __stcs(dA0 + t,       a0); __stcs(dA0 + t + 256, a1);
            __stcs(dB0 + t,       a0); __stcs(dB0 + t + 256, a1);
            __stcs(dA1 + t,       b0); __stcs(dA1 + t + 256, b1);
            __stcs(dB1 + t,       b0); __stcs(dB1 + t + 256, b1);
        }
        // y = [1]*n ++ [0]*n : 512 floats per block for the first 16 blocks
        if (p < 16) {
            const int base = p * 512;
            y_out[base + t]       = (base + t       < N_ROWS) ? 1.0f : 0.0f;
            y_out[base + 256 + t] = (base + 256 + t < N_ROWS) ? 1.0f : 0.0f;
        }
    }
}

// ---------------------------------------------------------------------------
// kernel_launch: inputs = d_in[0] (f32 4096x2048), targets = d_in[1] (i32 4096)
// out layout (flat f32): pair1 [2n*d] | pair2 [2n*d] | y [2n]
// ---------------------------------------------------------------------------
extern "C" void kernel_launch(void* const* d_in, const int* in_sizes, int n_in,
                              void* d_out, int out_size) {
    (void)in_sizes; (void)n_in; (void)out_size;
    const float* inputs  = (const float*)d_in[0];
    const int*   targets = (const int*)d_in[1];
    float*       out     = (float*)d_out;
    float*       y       = out + (size_t)4 * N_ROWS * DCOLS;  // after pair1|pair2

    fused_kernel<<<P2_BLOCKS + P1_BLOCKS, 256>>>(
        (const float4*)inputs, targets, (float4*)out, y);
}

// round 9
// speedup vs baseline: 1.0794x; 1.0306x over previous
#include <cuda_runtime.h>
#include <cstdint>

// Problem constants (fixed by the reference: n=4096, d=2048, num_ids=256)
#define N_ROWS 4096
#define DCOLS  2048
#define ROW_F4 (DCOLS / 4)   // 512 float4 per row
#define RPB    8             // rows per block
#define P2_BLOCKS (8192 / RPB)   // 1024  (pair2 first: scans overlap copies)
#define P1_BLOCKS (4096 / RPB)   // 512

// ---------------------------------------------------------------------------
// Bit-exact JAX threefry-2x32 (20 rounds)
// ---------------------------------------------------------------------------
__device__ __forceinline__ void threefry2x32(uint32_t k0, uint32_t k1,
                                             uint32_t c0, uint32_t c1,
                                             uint32_t& o0, uint32_t& o1) {
    const uint32_t ks2 = k0 ^ k1 ^ 0x1BD11BDAu;
    uint32_t x0 = c0 + k0;
    uint32_t x1 = c1 + k1;
#define TF_ROUND(r) { x0 += x1; x1 = (x1 << (r)) | (x1 >> (32 - (r))); x1 ^= x0; }
    TF_ROUND(13) TF_ROUND(15) TF_ROUND(26) TF_ROUND(6)
    x0 += k1;  x1 += ks2 + 1u;
    TF_ROUND(17) TF_ROUND(29) TF_ROUND(16) TF_ROUND(24)
    x0 += ks2; x1 += k0 + 2u;
    TF_ROUND(13) TF_ROUND(15) TF_ROUND(26) TF_ROUND(6)
    x0 += k0;  x1 += k1 + 3u;
    TF_ROUND(17) TF_ROUND(29) TF_ROUND(16) TF_ROUND(24)
    x0 += k1;  x1 += ks2 + 4u;
    TF_ROUND(13) TF_ROUND(15) TF_ROUND(26) TF_ROUND(6)
    x0 += ks2; x1 += k0 + 5u;
#undef TF_ROUND
    o0 = x0; o1 = x1;
}

// jax.random.uniform f32: bitcast(0x3F800000 | (bits >> 9)) - 1
__device__ __forceinline__ float bits_to_uniform(uint32_t b) {
    return __uint_as_float(0x3F800000u | (b >> 9)) - 1.0f;
}

// Partitionable threefry random bits for element i: counter=(0,i), out = o0^o1.
__device__ __forceinline__ uint32_t jax_bits32(uint32_t key_lo, uint32_t i) {
    uint32_t o0, o1;
    threefry2x32(0u, key_lo, 0u, i, o0, o1);
    return o0 ^ o1;
}

// Copy one row (512 float4) with 256 threads, loads batched 2-deep per row;
// caller interleaves two rows for 4-deep MLP.
__device__ __forceinline__ void copy2(const float4* __restrict__ sA,
                                      const float4* __restrict__ sB,
                                      float4* __restrict__ dA,
                                      float4* __restrict__ dB, int t) {
    const float4 a0 = __ldg(sA + t);
    const float4 a1 = __ldg(sA + t + 256);
    const float4 b0 = __ldg(sB + t);
    const float4 b1 = __ldg(sB + t + 256);
    __stcs(dA + t,       a0); __stcs(dA + t + 256, a1);
    __stcs(dB + t,       b0); __stcs(dB + t + 256, b1);
}

// ---------------------------------------------------------------------------
// fused_kernel, single launch, 1536 blocks x 256 threads.
//   Blocks [0, 1024):    pair2. Block q owns pair2 rows [q*8, q*8+8) of 8192.
//       Prologue: same-identity counts for the 8 rows via one pass over
//       targets (16 KB, L2-hot; 8 compares per loaded value), REDUX warp
//       reduction, then partitionable-threefry indices. Then gather-copy.
//   Blocks [1024, 1536): pair1. Block p owns input rows [p*8, p*8+8); each
//       float4 loaded once, stored to pair1 rows r and r+4096. First 16
//       blocks also write y.
// ---------------------------------------------------------------------------
__global__ void __launch_bounds__(256)
fused_kernel(const float4* __restrict__ in,
             const int* __restrict__ targets,
             float4* __restrict__ out,
             float* __restrict__ y_out) {
    const int t = threadIdx.x;
    const int b = blockIdx.x;

    if (b < P2_BLOCKS) {
        // ---------------- pair2 ----------------
        const int row0 = b * RPB;                  // pair2 row in [0, 8192)

        __shared__ int s_tgt[RPB];
        __shared__ int s_cnt[RPB];
        __shared__ int s_src[RPB];
        if (t < RPB) {
            s_tgt[t] = targets[(row0 + t) & (N_ROWS - 1)];
            s_cnt[t] = 0;
        }
        __syncthreads();

        // Counts: one coalesced pass over targets, 8 compares per value
        int c[RPB];
        #pragma unroll
        for (int j = 0; j < RPB; ++j) c[j] = 0;
        const int t0 = s_tgt[0], t1 = s_tgt[1], t2 = s_tgt[2], t3 = s_tgt[3];
        const int t4 = s_tgt[4], t5 = s_tgt[5], t6 = s_tgt[6], t7 = s_tgt[7];
        #pragma unroll
        for (int k = 0; k < N_ROWS / 256; ++k) {   // 16 L2-hot loads
            const int v = __ldg(&targets[k * 256 + t]);
            c[0] += (v == t0); c[1] += (v == t1); c[2] += (v == t2); c[3] += (v == t3);
            c[4] += (v == t4); c[5] += (v == t5); c[6] += (v == t6); c[7] += (v == t7);
        }
        #pragma unroll
        for (int j = 0; j < RPB; ++j)
            c[j] = __reduce_add_sync(0xFFFFFFFFu, c[j]);   // REDUX.SUM
        if ((t & 31) == 0) {
            #pragma unroll
            for (int j = 0; j < RPB; ++j) atomicAdd(&s_cnt[j], c[j]);
        }
        __syncthreads();

        if (t < RPB) {
            const int r  = row0 + t;
            const int i  = r & (N_ROWS - 1);       // element index for PRNG
            const int pc = s_cnt[t];
            int      cnt;
            uint32_t key;
            if (r < N_ROWS) { cnt = pc; key = 1u; }     // positives: key(1)
            else {
                cnt = N_ROWS - pc;
                if (cnt < 1) cnt = 1;
                key = 2u;                                // negatives: key(2)
            }
            const float u = bits_to_uniform(jax_bits32(key, (uint32_t)i));
            int idx = (int)(u * (float)cnt);             // f32 mul + trunc
            if (idx > cnt - 1) idx = cnt - 1;
            s_src[t] = idx;
        }
        __syncthreads();

        float4* base = out + (size_t)2 * N_ROWS * ROW_F4;  // start of pair2
        #pragma unroll
        for (int rp = 0; rp < RPB / 2; ++rp) {
            const int r0 = row0 + rp * 2;
            copy2(in + (size_t)s_src[rp * 2]     * ROW_F4,
                  in + (size_t)s_src[rp * 2 + 1] * ROW_F4,
                  base + (size_t)r0       * ROW_F4,
                  base + (size_t)(r0 + 1) * ROW_F4, t);
        }
    } else {
        // ---------------- pair1: dual store ----------------
        const int p    = b - P2_BLOCKS;
        const int row0 = p * RPB;                  // input row in [0, 4096)
        #pragma unroll
        for (int rr = 0; rr < RPB; rr += 2) {
            const int r0 = row0 + rr;
            const int r1 = r0 + 1;
            const float4* s0 = in + (size_t)r0 * ROW_F4;
            const float4* s1 = in + (size_t)r1 * ROW_F4;
            const float4 a0 = __ldg(s0 + t);
            const float4 a1 = __ldg(s0 + t + 256);
            const float4 b0 = __ldg(s1 + t);
            const float4 b1 = __ldg(s1 + t + 256);
            float4* dA0 = out + (size_t)r0 * ROW_F4;
            float4* dB0 = out + (size_t)(r0 + N_ROWS) * ROW_F4;
            float4* dA1 = out + (size_t)r1 * ROW_F4;
            float4* dB1 = out + (size_t)(r1 + N_ROWS) * ROW_F4;
            __stcs(dA0 + t,       a0); __stcs(dA0 + t + 256, a1);
            __stcs(dB0 + t,       a0); __stcs(dB0 + t + 256, a1);
            __stcs(dA1 + t,       b0); __stcs(dA1 + t + 256, b1);
            __stcs(dB1 + t,       b0); __stcs(dB1 + t + 256, b1);
        }
        // y = [1]*n ++ [0]*n : 512 floats per block for the first 16 blocks
        if (p < 16) {
            const int base = p * 512;
            y_out[base + t]       = (base + t       < N_ROWS) ? 1.0f : 0.0f;
            y_out[base + 256 + t] = (base + 256 + t < N_ROWS) ? 1.0f : 0.0f;
        }
    }
}

// ---------------------------------------------------------------------------
// kernel_launch: inputs = d_in[0] (f32 4096x2048), targets = d_in[1] (i32 4096)
// out layout (flat f32): pair1 [2n*d] | pair2 [2n*d] | y [2n]
// ---------------------------------------------------------------------------
extern "C" void kernel_launch(void* const* d_in, const int* in_sizes, int n_in,
                              void* d_out, int out_size) {
    (void)in_sizes; (void)n_in; (void)out_size;
    const float* inputs  = (const float*)d_in[0];
    const int*   targets = (const int*)d_in[1];
    float*       out     = (float*)d_out;
    float*       y       = out + (size_t)4 * N_ROWS * DCOLS;  // after pair1|pair2

    fused_kernel<<<P2_BLOCKS + P1_BLOCKS, 256>>>(
        (const float4*)inputs, targets, (float4*)out, y);
}